// round 16
// baseline (speedup 1.0000x reference)
#include <cuda_runtime.h>
#include <cuda_bf16.h>
#include <cuda_fp16.h>
#include <mma.h>
#include <cstdint>

using namespace nvcuda;

#define N_NODES 100000
#define N_EDGES 1600000
#define FDIM    128
#define N_GRAPHS 2048
#define NB_SCAN ((N_NODES + 1023) / 1024)   // 98
#define NT_TILES ((N_NODES + 127) / 128)    // 782 128-row tiles
#define TILE_SPLIT 391                      // lo half: tiles [0,391) = rows [0,50048)
#define NODE_SPLIT (TILE_SPLIT * 128)       // 50048
#define GEMM_GRID 148                       // one wave at 1 CTA/SM (512 threads)

// ---------------- scratch (static device globals; no allocation) ----------------
__device__ int      g_is64;
__device__ int      g_deg[N_NODES];
__device__ float    g_dis[N_NODES];
__device__ int      g_ptr[N_NODES + 1];
__device__ int      g_cur[N_NODES];
__device__ int      g_src[N_EDGES];
__device__ float    g_nrm[N_EDGES];
__device__ int      g_bsum[NB_SCAN];
__device__ __half   g_h[(size_t)N_NODES * FDIM];   // GEMM output (fp16)
__device__ __half   g_a[(size_t)N_NODES * FDIM];   // activations (fp16; holds x16 pre-layer-1)
__device__ float    g_cnt[N_GRAPHS];
__device__ __half   g_W16[4 * FDIM * FDIM];  // W rounded to fp16, per layer, [k][n]

// ---------------- side stream + events (created at load time) ----------------
struct StreamHolder {
    cudaStream_t s2 = nullptr;
    cudaEvent_t  ef = nullptr, ej = nullptr, ea = nullptr, eb = nullptr;
    bool ok = false;
    StreamHolder() {
        ok = (cudaStreamCreateWithFlags(&s2, cudaStreamNonBlocking) == cudaSuccess) &&
             (cudaEventCreateWithFlags(&ef, cudaEventDisableTiming) == cudaSuccess) &&
             (cudaEventCreateWithFlags(&ej, cudaEventDisableTiming) == cudaSuccess) &&
             (cudaEventCreateWithFlags(&ea, cudaEventDisableTiming) == cudaSuccess) &&
             (cudaEventCreateWithFlags(&eb, cudaEventDisableTiming) == cudaSuccess);
    }
};
static StreamHolder g_sh;

// index load for int32 or int64 buffers
__device__ __forceinline__ int load_idx(const void* buf, long long i, int is64) {
    if (is64) return (int)((const long long*)buf)[i];
    return ((const int*)buf)[i];
}

// cp.async helpers
__device__ __forceinline__ void cp_async16(void* sptr, const void* gptr, int src_bytes) {
    uint32_t sa = (uint32_t)__cvta_generic_to_shared(sptr);
    asm volatile("cp.async.cg.shared.global [%0], [%1], 16, %2;"
                 :: "r"(sa), "l"(gptr), "r"(src_bytes));
}
#define CP_COMMIT() asm volatile("cp.async.commit_group;" ::: "memory")
#define CP_WAIT0()  asm volatile("cp.async.wait_group 0;" ::: "memory")

// ---------------- dtype detection ----------------
__global__ void k_detect(const int* __restrict__ ei_raw) {
    if (threadIdx.x == 0 && blockIdx.x == 0) {
        int ornz = 0;
        for (int i = 0; i < 256; i++) ornz |= ei_raw[2 * i + 1];
        g_is64 = (ornz == 0) ? 1 : 0;
    }
}

// ---------------- W prep: plain fp16 round ----------------
__global__ void k_wprep(const float* __restrict__ W0, const float* __restrict__ W1,
                        const float* __restrict__ W2, const float* __restrict__ W3) {
    int t = blockIdx.x * blockDim.x + threadIdx.x;
    if (t >= 4 * FDIM * FDIM) return;
    int layer = t >> 14;
    int i = t & (FDIM * FDIM - 1);
    const float* W = (layer == 0) ? W0 : (layer == 1) ? W1 : (layer == 2) ? W2 : W3;
    g_W16[t] = __float2half_rn(W[i]);
}

// ---------------- x -> fp16 ----------------
__global__ void k_xconv(const float* __restrict__ x, __half* __restrict__ out) {
    int i = blockIdx.x * blockDim.x + threadIdx.x;            // float4 index
    if (i >= N_NODES * FDIM / 4) return;
    float4 f = ((const float4*)x)[i];
    __half2 p0 = __floats2half2_rn(f.x, f.y);
    __half2 p1 = __floats2half2_rn(f.z, f.w);
    uint2 pk;
    pk.x = *(uint32_t*)&p0;
    pk.y = *(uint32_t*)&p1;
    ((uint2*)out)[i] = pk;
}

// ---------------- preprocessing ----------------
__global__ void k_zero_deg() {
    int i = blockIdx.x * blockDim.x + threadIdx.x;
    if (i < N_NODES) g_deg[i] = 0;
}
__global__ void k_count(const void* __restrict__ ei) {
    int e = blockIdx.x * blockDim.x + threadIdx.x;
    int is64 = g_is64;
    if (e < N_EDGES) {
        int c = load_idx(ei, (long long)N_EDGES + e, is64);
        atomicAdd(&g_deg[c], 1);
    }
}
__global__ void k_dis() {
    int i = blockIdx.x * blockDim.x + threadIdx.x;
    if (i < N_NODES) g_dis[i] = rsqrtf((float)(g_deg[i] + 1));
}
__global__ void k_scan1() {
    __shared__ int s[1024];
    int i = blockIdx.x * 1024 + threadIdx.x;
    int v = (i < N_NODES) ? g_deg[i] : 0;
    s[threadIdx.x] = v;
    __syncthreads();
#pragma unroll
    for (int off = 1; off < 1024; off <<= 1) {
        int t = 0;
        if ((int)threadIdx.x >= off) t = s[threadIdx.x - off];
        __syncthreads();
        s[threadIdx.x] += t;
        __syncthreads();
    }
    if (i < N_NODES) g_ptr[i] = s[threadIdx.x] - v;
    if (threadIdx.x == 1023) g_bsum[blockIdx.x] = s[1023];
}
__global__ void k_scan2() {
    __shared__ int s[128];
    int v = ((int)threadIdx.x < NB_SCAN) ? g_bsum[threadIdx.x] : 0;
    s[threadIdx.x] = v;
    __syncthreads();
#pragma unroll
    for (int off = 1; off < 128; off <<= 1) {
        int t = 0;
        if ((int)threadIdx.x >= off) t = s[threadIdx.x - off];
        __syncthreads();
        s[threadIdx.x] += t;
        __syncthreads();
    }
    if ((int)threadIdx.x < NB_SCAN) g_bsum[threadIdx.x] = s[threadIdx.x] - v;
}
__global__ void k_scan3() {
    int i = blockIdx.x * 1024 + threadIdx.x;
    if (i < N_NODES) {
        g_ptr[i] += g_bsum[blockIdx.x];
        g_cur[i] = g_ptr[i];
    }
    if (i == 0) g_ptr[N_NODES] = N_EDGES;
}
__global__ void k_fill(const void* __restrict__ ei) {
    int e = blockIdx.x * blockDim.x + threadIdx.x;
    int is64 = g_is64;
    if (e < N_EDGES) {
        int r = load_idx(ei, e, is64);
        int c = load_idx(ei, (long long)N_EDGES + e, is64);
        int pos = atomicAdd(&g_cur[c], 1);
        g_src[pos] = r;
        g_nrm[pos] = g_dis[r] * g_dis[c];
    }
}

// ---------------- WMMA GEMM: persistent, B-stationary, tile range [tbeg,tend) -------
#define LDSW 136   // W padded leading dim (halves)
#define LDSA 136   // A padded leading dim (halves)

__global__ void __launch_bounds__(512, 1) k_gemm_wmma(const __half* __restrict__ A,
                                                      const __half* __restrict__ W16,
                                                      __half* __restrict__ C, int n,
                                                      int tbeg, int tend) {
    extern __shared__ __half sm[];
    __half* sW  = sm;                                  // [128][LDSW]
    __half* sA0 = sm + 128 * LDSW;                     // [128][LDSA] buffer 0
    __half* sA1 = sA0 + 128 * LDSA;                    // [128][LDSA] buffer 1

    const int tid = threadIdx.x;
    const int t0 = tbeg + blockIdx.x;
    if (t0 >= tend) return;

    // W via cp.async (always in-bounds)
    for (int i = tid; i < 128 * 16; i += 512) {
        int k  = i >> 4;
        int c8 = (i & 15) << 3;
        cp_async16(sW + k * LDSW + c8, W16 + k * FDIM + c8, 16);
    }
    // first A tile (128 rows) into buffer 0
    for (int i = tid; i < 128 * 16; i += 512) {
        int r  = i >> 4;
        int c8 = (i & 15) << 3;
        long long grow = (long long)t0 * 128 + r;
        bool ok = grow < n;
        const __half* src = ok ? (A + grow * FDIM + c8) : A;
        cp_async16(sA0 + r * LDSA + c8, src, ok ? 16 : 0);
    }
    CP_COMMIT();
    CP_WAIT0();
    __syncthreads();

    const int w  = tid >> 5;
    const int wr = (w & 3) * 32;     // warp row offset within 128-row tile
    const int wc = (w >> 2) * 32;    // warp col offset (0..96)

    // B-stationary: 16 fragments (8 k-steps x 2 col frags)
    wmma::fragment<wmma::matrix_b, 16, 16, 16, __half, wmma::row_major> b[8][2];
#pragma unroll
    for (int k = 0; k < 8; k++)
#pragma unroll
        for (int j = 0; j < 2; j++)
            wmma::load_matrix_sync(b[k][j], sW + k * 16 * LDSW + wc + 16 * j, LDSW);

    int cur = 0;
    for (int t = t0; t < tend; t += GEMM_GRID) {
        const int tn = t + GEMM_GRID;
        __half* bufc = cur ? sA1 : sA0;
        __half* bufn = cur ? sA0 : sA1;

        // prefetch next tile (overlaps with MMA below)
        if (tn < tend) {
            for (int i = tid; i < 128 * 16; i += 512) {
                int r  = i >> 4;
                int c8 = (i & 15) << 3;
                long long grow = (long long)tn * 128 + r;
                bool ok = grow < n;
                const __half* src = ok ? (A + grow * FDIM + c8) : A;
                cp_async16(bufn + r * LDSA + c8, src, ok ? 16 : 0);
            }
            CP_COMMIT();
        }

        // MMA: 4 independent chains (2 rows x 2 cols)
        wmma::fragment<wmma::accumulator, 16, 16, 16, float> acc[2][2];
#pragma unroll
        for (int i = 0; i < 2; i++)
#pragma unroll
            for (int j = 0; j < 2; j++) wmma::fill_fragment(acc[i][j], 0.0f);

#pragma unroll
        for (int k = 0; k < 8; k++) {
            wmma::fragment<wmma::matrix_a, 16, 16, 16, __half, wmma::row_major> a[2];
#pragma unroll
            for (int i = 0; i < 2; i++)
                wmma::load_matrix_sync(a[i], bufc + (wr + 16 * i) * LDSA + k * 16, LDSA);
#pragma unroll
            for (int i = 0; i < 2; i++)
#pragma unroll
                for (int j = 0; j < 2; j++)
                    wmma::mma_sync(acc[i][j], a[i], b[k][j], acc[i][j]);
        }

        // epilogue: fp32 -> fp16 frag, direct store (frag-level guard exact: n % 16 == 0)
        wmma::fragment<wmma::accumulator, 16, 16, 16, __half> hc;
#pragma unroll
        for (int i = 0; i < 2; i++) {
            long long grow = (long long)t * 128 + wr + 16 * i;
            if (grow + 16 <= n) {
#pragma unroll
                for (int j = 0; j < 2; j++) {
#pragma unroll
                    for (int e = 0; e < hc.num_elements; e++)
                        hc.x[e] = __float2half_rn(acc[i][j].x[e]);
                    wmma::store_matrix_sync(C + grow * FDIM + wc + 16 * j,
                                            hc, FDIM, wmma::mem_row_major);
                }
            }
        }

        if (tn < tend) CP_WAIT0();
        __syncthreads();
        cur ^= 1;
    }
}

// ---------------- aggregation over node range [noff, noff+ncnt) ----------------
__global__ void k_agg(const __half* __restrict__ h, const float* __restrict__ bias,
                      __half* __restrict__ out, int noff, int ncnt) {
    int idx = (blockIdx.x * blockDim.x + threadIdx.x) >> 5;
    if (idx >= ncnt) return;
    int node = noff + idx;
    int lane = threadIdx.x & 31;

    int beg = g_ptr[node];
    int end = g_ptr[node + 1];
    float sn = 1.0f / (float)(g_deg[node] + 1);

    float4 acc;
    {
        uint2 u = ((const uint2*)(h + (size_t)node * FDIM))[lane];
        float2 f0 = __half22float2(*(__half2*)&u.x);
        float2 f1 = __half22float2(*(__half2*)&u.y);
        acc = make_float4(sn * f0.x, sn * f0.y, sn * f1.x, sn * f1.y);
    }

    int e = beg;
    for (; e + 8 <= end; e += 8) {
        int   rr[8];
        float ww[8];
        uint2 uu[8];
#pragma unroll
        for (int j = 0; j < 8; j++) { rr[j] = g_src[e + j]; ww[j] = g_nrm[e + j]; }
#pragma unroll
        for (int j = 0; j < 8; j++)
            uu[j] = ((const uint2*)(h + (size_t)rr[j] * FDIM))[lane];
#pragma unroll
        for (int j = 0; j < 8; j++) {
            float2 f0 = __half22float2(*(__half2*)&uu[j].x);
            float2 f1 = __half22float2(*(__half2*)&uu[j].y);
            acc.x += ww[j] * f0.x;
            acc.y += ww[j] * f0.y;
            acc.z += ww[j] * f1.x;
            acc.w += ww[j] * f1.y;
        }
    }
    for (; e < end; e++) {
        int   r = g_src[e];
        float w = g_nrm[e];
        uint2 u = ((const uint2*)(h + (size_t)r * FDIM))[lane];
        float2 f0 = __half22float2(*(__half2*)&u.x);
        float2 f1 = __half22float2(*(__half2*)&u.y);
        acc.x += w * f0.x;
        acc.y += w * f0.y;
        acc.z += w * f1.x;
        acc.w += w * f1.y;
    }
    float4 bb = ((const float4*)bias)[lane];
    acc.x = fmaxf(acc.x + bb.x, 0.0f);
    acc.y = fmaxf(acc.y + bb.y, 0.0f);
    acc.z = fmaxf(acc.z + bb.z, 0.0f);
    acc.w = fmaxf(acc.w + bb.w, 0.0f);
    __half2 p0 = __floats2half2_rn(acc.x, acc.y);
    __half2 p1 = __floats2half2_rn(acc.z, acc.w);
    uint2 pk;
    pk.x = *(uint32_t*)&p0;
    pk.y = *(uint32_t*)&p1;
    ((uint2*)(out + (size_t)node * FDIM))[lane] = pk;
}

// ---------------- pooling over node range (sorted batch -> segmented sum) -----------
__global__ void k_pool_zero(float* __restrict__ out) {
    int i = blockIdx.x * blockDim.x + threadIdx.x;
    if (i < N_GRAPHS * FDIM) out[i] = 0.0f;
    if (i < N_GRAPHS) g_cnt[i] = 0.0f;
}
__global__ void k_pool_seg(const __half* __restrict__ a, const void* __restrict__ batch,
                           float* __restrict__ out, int noff, int ncnt) {
    int b0 = noff + blockIdx.x * 128;
    int nend = min(noff + ncnt, b0 + 128);
    if (b0 >= noff + ncnt) return;
    int f = threadIdx.x;
    int is64 = g_is64;

    float acc = 0.0f;
    int cnt = 0;
    int cur = load_idx(batch, b0, is64);
    for (int node = b0; node < nend; node++) {
        int g = load_idx(batch, node, is64);
        if (g != cur) {
            atomicAdd(&out[(size_t)cur * FDIM + f], acc);
            if (f == 0) atomicAdd(&g_cnt[cur], (float)cnt);
            acc = 0.0f; cnt = 0; cur = g;
        }
        acc += __half2float(a[(size_t)node * FDIM + f]);
        cnt++;
    }
    atomicAdd(&out[(size_t)cur * FDIM + f], acc);
    if (f == 0) atomicAdd(&g_cnt[cur], (float)cnt);
}
__global__ void k_pool_div(float* __restrict__ out) {
    int i = blockIdx.x * blockDim.x + threadIdx.x;
    if (i < N_GRAPHS * FDIM) out[i] /= fmaxf(g_cnt[i >> 7], 1.0f);
}

// ---------------- launch ----------------
extern "C" void kernel_launch(void* const* d_in, const int* in_sizes, int n_in,
                              void* d_out, int out_size) {
    const float* x = nullptr;
    const float* W[4] = {nullptr, nullptr, nullptr, nullptr};
    const float* b[4] = {nullptr, nullptr, nullptr, nullptr};
    const void* ei = nullptr;
    const void* batch = nullptr;
    int nw = 0, nb = 0;
    for (int i = 0; i < n_in; i++) {
        switch (in_sizes[i]) {
            case N_NODES * FDIM:      x = (const float*)d_in[i]; break;
            case FDIM * FDIM:         if (nw < 4) W[nw++] = (const float*)d_in[i]; break;
            case FDIM:                if (nb < 4) b[nb++] = (const float*)d_in[i]; break;
            case 2 * N_EDGES:         ei = d_in[i]; break;
            case N_NODES:             batch = d_in[i]; break;
            default: break;
        }
    }
    if (!x && n_in >= 11) {
        x = (const float*)d_in[0];
        W[0] = (const float*)d_in[1]; b[0] = (const float*)d_in[2];
        W[1] = (const float*)d_in[3]; b[1] = (const float*)d_in[4];
        W[2] = (const float*)d_in[5]; b[2] = (const float*)d_in[6];
        W[3] = (const float*)d_in[7]; b[3] = (const float*)d_in[8];
        ei = d_in[9]; batch = d_in[10];
    }
    float* out = (float*)d_out;

    __half* gh; cudaGetSymbolAddress((void**)&gh, g_h);
    __half* ga; cudaGetSymbolAddress((void**)&ga, g_a);
    __half* gw; cudaGetSymbolAddress((void**)&gw, g_W16);

    const int GEMM_SMEM = (128 * LDSW + 2 * 128 * LDSA) * (int)sizeof(__half);  // 104448
    cudaFuncSetAttribute(k_gemm_wmma, cudaFuncAttributeMaxDynamicSharedMemorySize, GEMM_SMEM);

    const int TPB = 256;
    const int NODES_LO = NODE_SPLIT;              // 50048
    const int NODES_HI = N_NODES - NODE_SPLIT;    // 49952
    const int agg_lo_blocks = (NODES_LO * 32 + TPB - 1) / TPB;
    const int agg_hi_blocks = (NODES_HI * 32 + TPB - 1) / TPB;
    const int agg_all_blocks = (N_NODES * 32 + TPB - 1) / TPB;
    const int seg_lo_blocks = (NODES_LO + 127) / 128;
    const int seg_hi_blocks = (NODES_HI + 127) / 128;

    const bool fork = g_sh.ok;
    cudaStream_t s2 = fork ? g_sh.s2 : (cudaStream_t)0;

    // detect first (preproc needs g_is64), then fork preproc to side stream
    k_detect<<<1, 32>>>((const int*)ei);
    if (fork) {
        cudaEventRecord(g_sh.ef, 0);
        cudaStreamWaitEvent(s2, g_sh.ef, 0);
    }

    // side stream: graph preprocessing + pool zero
    k_zero_deg<<<(N_NODES + TPB - 1) / TPB, TPB, 0, s2>>>();
    k_count<<<(N_EDGES + TPB - 1) / TPB, TPB, 0, s2>>>(ei);
    k_dis<<<(N_NODES + TPB - 1) / TPB, TPB, 0, s2>>>();
    k_scan1<<<NB_SCAN, 1024, 0, s2>>>();
    k_scan2<<<1, 128, 0, s2>>>();
    k_scan3<<<NB_SCAN, 1024, 0, s2>>>();
    k_fill<<<(N_EDGES + TPB - 1) / TPB, TPB, 0, s2>>>(ei);
    k_pool_zero<<<(N_GRAPHS * FDIM + TPB - 1) / TPB, TPB, 0, s2>>>(out);
    if (fork) cudaEventRecord(g_sh.ej, s2);

    // main stream: W prep + x conversion + layer-1 GEMM (full range)
    k_wprep<<<(4 * FDIM * FDIM + TPB - 1) / TPB, TPB>>>(W[0], W[1], W[2], W[3]);
    k_xconv<<<(N_NODES * FDIM / 4 + TPB - 1) / TPB, TPB>>>(x, ga);
    k_gemm_wmma<<<GEMM_GRID, 512, GEMM_SMEM>>>(ga, gw + 0 * FDIM * FDIM, gh, N_NODES, 0, NT_TILES);

    if (fork) cudaStreamWaitEvent(0, g_sh.ej, 0);   // join: agg needs CSR

    if (fork) {
        // pipelined layers: A^lo -> {A^hi || G^lo} -> G^hi
        for (int l = 0; l < 3; l++) {
            k_agg<<<agg_lo_blocks, TPB>>>(gh, b[l], ga, 0, NODES_LO);
            cudaEventRecord(g_sh.ea, 0);
            cudaStreamWaitEvent(s2, g_sh.ea, 0);
            k_agg<<<agg_hi_blocks, TPB, 0, s2>>>(gh, b[l], ga, NODE_SPLIT, NODES_HI);
            cudaEventRecord(g_sh.eb, s2);
            k_gemm_wmma<<<GEMM_GRID, 512, GEMM_SMEM>>>(ga, gw + (l + 1) * FDIM * FDIM, gh,
                                                       N_NODES, 0, TILE_SPLIT);
            cudaStreamWaitEvent(0, g_sh.eb, 0);
            k_gemm_wmma<<<GEMM_GRID, 512, GEMM_SMEM>>>(ga, gw + (l + 1) * FDIM * FDIM, gh,
                                                       N_NODES, TILE_SPLIT, NT_TILES);
        }
        // layer 4: A^lo -> {A^hi || pool^lo} -> pool^hi -> div
        k_agg<<<agg_lo_blocks, TPB>>>(gh, b[3], ga, 0, NODES_LO);
        cudaEventRecord(g_sh.ea, 0);
        cudaStreamWaitEvent(s2, g_sh.ea, 0);
        k_agg<<<agg_hi_blocks, TPB, 0, s2>>>(gh, b[3], ga, NODE_SPLIT, NODES_HI);
        cudaEventRecord(g_sh.eb, s2);
        k_pool_seg<<<seg_lo_blocks, 128>>>(ga, batch, out, 0, NODES_LO);
        cudaStreamWaitEvent(0, g_sh.eb, 0);
        k_pool_seg<<<seg_hi_blocks, 128>>>(ga, batch, out, NODE_SPLIT, NODES_HI);
        k_pool_div<<<(N_GRAPHS * FDIM + TPB - 1) / TPB, TPB>>>(out);
    } else {
        // sequential fallback
        for (int l = 0; l < 3; l++) {
            k_agg<<<agg_all_blocks, TPB>>>(gh, b[l], ga, 0, N_NODES);
            k_gemm_wmma<<<GEMM_GRID, 512, GEMM_SMEM>>>(ga, gw + (l + 1) * FDIM * FDIM, gh,
                                                       N_NODES, 0, NT_TILES);
        }
        k_agg<<<agg_all_blocks, TPB>>>(gh, b[3], ga, 0, N_NODES);
        k_pool_seg<<<seg_lo_blocks, 128>>>(ga, batch, out, 0, NODES_LO);
        k_pool_seg<<<seg_hi_blocks, 128>>>(ga, batch, out, NODE_SPLIT, NODES_HI);
        k_pool_div<<<(N_GRAPHS * FDIM + TPB - 1) / TPB, TPB>>>(out);
    }
}

// round 17
// speedup vs baseline: 1.1086x; 1.1086x over previous
#include <cuda_runtime.h>
#include <cuda_bf16.h>
#include <cuda_fp16.h>
#include <mma.h>
#include <cstdint>

using namespace nvcuda;

#define N_NODES 100000
#define N_EDGES 1600000
#define FDIM    128
#define N_GRAPHS 2048
#define NB_SCAN ((N_NODES + 1023) / 1024)   // 98
#define NT_TILES ((N_NODES + 127) / 128)    // 782 128-row tiles
#define GEMM_GRID 148                       // one wave at 1 CTA/SM (512 threads)

// ---------------- scratch (static device globals; no allocation) ----------------
__device__ int      g_is64;
__device__ int      g_deg[N_NODES];
__device__ float    g_dis[N_NODES];
__device__ int      g_ptr[N_NODES + 1];
__device__ int      g_cur[N_NODES];
__device__ int      g_src[N_EDGES];
__device__ float    g_nrm[N_EDGES];
__device__ int      g_bsum[NB_SCAN];
__device__ __half   g_h[(size_t)N_NODES * FDIM];   // GEMM output (fp16)
__device__ __half   g_a[(size_t)N_NODES * FDIM];   // activations (fp16)
__device__ float    g_cnt[N_GRAPHS];
__device__ __half   g_W16[4 * FDIM * FDIM];  // W rounded to fp16, per layer, [k][n]

// ---------------- side stream ----------------
struct StreamHolder {
    cudaStream_t s2 = nullptr;
    cudaEvent_t  ef = nullptr, ej = nullptr;
    bool ok = false;
    StreamHolder() {
        ok = (cudaStreamCreateWithFlags(&s2, cudaStreamNonBlocking) == cudaSuccess) &&
             (cudaEventCreateWithFlags(&ef, cudaEventDisableTiming) == cudaSuccess) &&
             (cudaEventCreateWithFlags(&ej, cudaEventDisableTiming) == cudaSuccess);
    }
};
static StreamHolder g_sh;

// index load for int32 or int64 buffers
__device__ __forceinline__ int load_idx(const void* buf, long long i, int is64) {
    if (is64) return (int)((const long long*)buf)[i];
    return ((const int*)buf)[i];
}

// cp.async helpers
__device__ __forceinline__ void cp_async16(void* sptr, const void* gptr, int src_bytes) {
    uint32_t sa = (uint32_t)__cvta_generic_to_shared(sptr);
    asm volatile("cp.async.cg.shared.global [%0], [%1], 16, %2;"
                 :: "r"(sa), "l"(gptr), "r"(src_bytes));
}
#define CP_COMMIT() asm volatile("cp.async.commit_group;" ::: "memory")
#define CP_WAIT0()  asm volatile("cp.async.wait_group 0;" ::: "memory")

// ---------------- dtype detection ----------------
__global__ void k_detect(const int* __restrict__ ei_raw) {
    if (threadIdx.x == 0 && blockIdx.x == 0) {
        int ornz = 0;
        for (int i = 0; i < 256; i++) ornz |= ei_raw[2 * i + 1];
        g_is64 = (ornz == 0) ? 1 : 0;
    }
}

// ---------------- W prep: plain fp16 round ----------------
__global__ void k_wprep(const float* __restrict__ W0, const float* __restrict__ W1,
                        const float* __restrict__ W2, const float* __restrict__ W3) {
    int t = blockIdx.x * blockDim.x + threadIdx.x;
    if (t >= 4 * FDIM * FDIM) return;
    int layer = t >> 14;
    int i = t & (FDIM * FDIM - 1);
    const float* W = (layer == 0) ? W0 : (layer == 1) ? W1 : (layer == 2) ? W2 : W3;
    g_W16[t] = __float2half_rn(W[i]);
}

// ---------------- preprocessing ----------------
__global__ void k_zero_deg() {
    int i = blockIdx.x * blockDim.x + threadIdx.x;
    if (i < N_NODES) g_deg[i] = 0;
}
__global__ void k_count(const void* __restrict__ ei) {
    int e = blockIdx.x * blockDim.x + threadIdx.x;
    int is64 = g_is64;
    if (e < N_EDGES) {
        int c = load_idx(ei, (long long)N_EDGES + e, is64);
        atomicAdd(&g_deg[c], 1);
    }
}
// scan1 also computes g_dis (fused former k_dis)
__global__ void k_scan1() {
    __shared__ int s[1024];
    int i = blockIdx.x * 1024 + threadIdx.x;
    int v = (i < N_NODES) ? g_deg[i] : 0;
    if (i < N_NODES) g_dis[i] = rsqrtf((float)(v + 1));
    s[threadIdx.x] = v;
    __syncthreads();
#pragma unroll
    for (int off = 1; off < 1024; off <<= 1) {
        int t = 0;
        if ((int)threadIdx.x >= off) t = s[threadIdx.x - off];
        __syncthreads();
        s[threadIdx.x] += t;
        __syncthreads();
    }
    if (i < N_NODES) g_ptr[i] = s[threadIdx.x] - v;
    if (threadIdx.x == 1023) g_bsum[blockIdx.x] = s[1023];
}
__global__ void k_scan2() {
    __shared__ int s[128];
    int v = ((int)threadIdx.x < NB_SCAN) ? g_bsum[threadIdx.x] : 0;
    s[threadIdx.x] = v;
    __syncthreads();
#pragma unroll
    for (int off = 1; off < 128; off <<= 1) {
        int t = 0;
        if ((int)threadIdx.x >= off) t = s[threadIdx.x - off];
        __syncthreads();
        s[threadIdx.x] += t;
        __syncthreads();
    }
    if ((int)threadIdx.x < NB_SCAN) g_bsum[threadIdx.x] = s[threadIdx.x] - v;
}
__global__ void k_scan3() {
    int i = blockIdx.x * 1024 + threadIdx.x;
    if (i < N_NODES) {
        g_ptr[i] += g_bsum[blockIdx.x];
        g_cur[i] = g_ptr[i];
    }
    if (i == 0) g_ptr[N_NODES] = N_EDGES;
}
__global__ void k_fill(const void* __restrict__ ei) {
    int e = blockIdx.x * blockDim.x + threadIdx.x;
    int is64 = g_is64;
    if (e < N_EDGES) {
        int r = load_idx(ei, e, is64);
        int c = load_idx(ei, (long long)N_EDGES + e, is64);
        int pos = atomicAdd(&g_cur[c], 1);
        g_src[pos] = r;
        g_nrm[pos] = g_dis[r] * g_dis[c];
    }
}

#define LDSW 136   // W padded leading dim (halves)
#define LDSA 136   // A padded leading dim (halves)

// ---------------- WMMA GEMM (fp16 input): persistent, B-stationary, double-buffered -
__global__ void __launch_bounds__(512, 1) k_gemm_wmma(const __half* __restrict__ A,
                                                      const __half* __restrict__ W16,
                                                      __half* __restrict__ C, int n) {
    extern __shared__ __half sm[];
    __half* sW  = sm;                                  // [128][LDSW]
    __half* sA0 = sm + 128 * LDSW;                     // [128][LDSA] buffer 0
    __half* sA1 = sA0 + 128 * LDSA;                    // [128][LDSA] buffer 1

    const int tid = threadIdx.x;
    const int t0 = blockIdx.x;

    for (int i = tid; i < 128 * 16; i += 512) {
        int k  = i >> 4;
        int c8 = (i & 15) << 3;
        cp_async16(sW + k * LDSW + c8, W16 + k * FDIM + c8, 16);
    }
    for (int i = tid; i < 128 * 16; i += 512) {
        int r  = i >> 4;
        int c8 = (i & 15) << 3;
        long long grow = (long long)t0 * 128 + r;
        bool ok = grow < n;
        const __half* src = ok ? (A + grow * FDIM + c8) : A;
        cp_async16(sA0 + r * LDSA + c8, src, ok ? 16 : 0);
    }
    CP_COMMIT();
    CP_WAIT0();
    __syncthreads();

    const int w  = tid >> 5;
    const int wr = (w & 3) * 32;
    const int wc = (w >> 2) * 32;

    wmma::fragment<wmma::matrix_b, 16, 16, 16, __half, wmma::row_major> b[8][2];
#pragma unroll
    for (int k = 0; k < 8; k++)
#pragma unroll
        for (int j = 0; j < 2; j++)
            wmma::load_matrix_sync(b[k][j], sW + k * 16 * LDSW + wc + 16 * j, LDSW);

    int cur = 0;
    for (int t = t0; t < NT_TILES; t += GEMM_GRID) {
        const int tn = t + GEMM_GRID;
        __half* bufc = cur ? sA1 : sA0;
        __half* bufn = cur ? sA0 : sA1;

        if (tn < NT_TILES) {
            for (int i = tid; i < 128 * 16; i += 512) {
                int r  = i >> 4;
                int c8 = (i & 15) << 3;
                long long grow = (long long)tn * 128 + r;
                bool ok = grow < n;
                const __half* src = ok ? (A + grow * FDIM + c8) : A;
                cp_async16(bufn + r * LDSA + c8, src, ok ? 16 : 0);
            }
            CP_COMMIT();
        }

        wmma::fragment<wmma::accumulator, 16, 16, 16, float> acc[2][2];
#pragma unroll
        for (int i = 0; i < 2; i++)
#pragma unroll
            for (int j = 0; j < 2; j++) wmma::fill_fragment(acc[i][j], 0.0f);

#pragma unroll
        for (int k = 0; k < 8; k++) {
            wmma::fragment<wmma::matrix_a, 16, 16, 16, __half, wmma::row_major> a[2];
#pragma unroll
            for (int i = 0; i < 2; i++)
                wmma::load_matrix_sync(a[i], bufc + (wr + 16 * i) * LDSA + k * 16, LDSA);
#pragma unroll
            for (int i = 0; i < 2; i++)
#pragma unroll
                for (int j = 0; j < 2; j++)
                    wmma::mma_sync(acc[i][j], a[i], b[k][j], acc[i][j]);
        }

        wmma::fragment<wmma::accumulator, 16, 16, 16, __half> hc;
#pragma unroll
        for (int i = 0; i < 2; i++) {
            long long grow = (long long)t * 128 + wr + 16 * i;
            if (grow + 16 <= n) {
#pragma unroll
                for (int j = 0; j < 2; j++) {
#pragma unroll
                    for (int e = 0; e < hc.num_elements; e++)
                        hc.x[e] = __float2half_rn(acc[i][j].x[e]);
                    wmma::store_matrix_sync(C + grow * FDIM + wc + 16 * j,
                                            hc, FDIM, wmma::mem_row_major);
                }
            }
        }

        if (tn < NT_TILES) CP_WAIT0();
        __syncthreads();
        cur ^= 1;
    }
}

// ---------------- WMMA GEMM variant: fp32 input (layer 1; replaces k_xconv) ---------
// Single A buffer; load fp32 -> convert -> smem fp16 each tile, then MMA.
__global__ void __launch_bounds__(512, 1) k_gemm_f32(const float* __restrict__ A,
                                                     const __half* __restrict__ W16,
                                                     __half* __restrict__ C, int n) {
    extern __shared__ __half sm[];
    __half* sW = sm;                                   // [128][LDSW]
    __half* sA = sm + 128 * LDSW;                      // [128][LDSA]

    const int tid = threadIdx.x;
    const int t0 = blockIdx.x;

    for (int i = tid; i < 128 * 16; i += 512) {
        int k  = i >> 4;
        int c8 = (i & 15) << 3;
        cp_async16(sW + k * LDSW + c8, W16 + k * FDIM + c8, 16);
    }
    CP_COMMIT();
    CP_WAIT0();
    __syncthreads();

    const int w  = tid >> 5;
    const int wr = (w & 3) * 32;
    const int wc = (w >> 2) * 32;

    wmma::fragment<wmma::matrix_b, 16, 16, 16, __half, wmma::row_major> b[8][2];
#pragma unroll
    for (int k = 0; k < 8; k++)
#pragma unroll
        for (int j = 0; j < 2; j++)
            wmma::load_matrix_sync(b[k][j], sW + k * 16 * LDSW + wc + 16 * j, LDSW);
    __syncthreads();

    for (int t = t0; t < NT_TILES; t += GEMM_GRID) {
        // load fp32 tile, convert to fp16 in smem (128 rows x 32 float4)
        for (int i = tid; i < 128 * 32; i += 512) {
            int r  = i >> 5;
            int c4 = (i & 31) << 2;
            long long grow = (long long)t * 128 + r;
            float4 f = (grow < n) ? *(const float4*)(A + grow * FDIM + c4)
                                  : make_float4(0.f, 0.f, 0.f, 0.f);
            __half2 p0 = __floats2half2_rn(f.x, f.y);
            __half2 p1 = __floats2half2_rn(f.z, f.w);
            uint2 pk;
            pk.x = *(uint32_t*)&p0;
            pk.y = *(uint32_t*)&p1;
            *(uint2*)(sA + r * LDSA + c4) = pk;
        }
        __syncthreads();

        wmma::fragment<wmma::accumulator, 16, 16, 16, float> acc[2][2];
#pragma unroll
        for (int i = 0; i < 2; i++)
#pragma unroll
            for (int j = 0; j < 2; j++) wmma::fill_fragment(acc[i][j], 0.0f);

#pragma unroll
        for (int k = 0; k < 8; k++) {
            wmma::fragment<wmma::matrix_a, 16, 16, 16, __half, wmma::row_major> a[2];
#pragma unroll
            for (int i = 0; i < 2; i++)
                wmma::load_matrix_sync(a[i], sA + (wr + 16 * i) * LDSA + k * 16, LDSA);
#pragma unroll
            for (int i = 0; i < 2; i++)
#pragma unroll
                for (int j = 0; j < 2; j++)
                    wmma::mma_sync(acc[i][j], a[i], b[k][j], acc[i][j]);
        }

        wmma::fragment<wmma::accumulator, 16, 16, 16, __half> hc;
#pragma unroll
        for (int i = 0; i < 2; i++) {
            long long grow = (long long)t * 128 + wr + 16 * i;
            if (grow + 16 <= n) {
#pragma unroll
                for (int j = 0; j < 2; j++) {
#pragma unroll
                    for (int e = 0; e < hc.num_elements; e++)
                        hc.x[e] = __float2half_rn(acc[i][j].x[e]);
                    wmma::store_matrix_sync(C + grow * FDIM + wc + 16 * j,
                                            hc, FDIM, wmma::mem_row_major);
                }
            }
        }
        __syncthreads();
    }
}

// ---------------- aggregation: fp16 gather, fp32 accumulate, fp16 out ----------------
__global__ void k_agg(const __half* __restrict__ h, const float* __restrict__ bias,
                      __half* __restrict__ out) {
    int node = (blockIdx.x * blockDim.x + threadIdx.x) >> 5;
    if (node >= N_NODES) return;
    int lane = threadIdx.x & 31;

    int beg = g_ptr[node];
    int end = g_ptr[node + 1];
    float sn = 1.0f / (float)(g_deg[node] + 1);

    float4 acc;
    {
        uint2 u = ((const uint2*)(h + (size_t)node * FDIM))[lane];
        float2 f0 = __half22float2(*(__half2*)&u.x);
        float2 f1 = __half22float2(*(__half2*)&u.y);
        acc = make_float4(sn * f0.x, sn * f0.y, sn * f1.x, sn * f1.y);
    }

    int e = beg;
    for (; e + 8 <= end; e += 8) {
        int   rr[8];
        float ww[8];
        uint2 uu[8];
#pragma unroll
        for (int j = 0; j < 8; j++) { rr[j] = g_src[e + j]; ww[j] = g_nrm[e + j]; }
#pragma unroll
        for (int j = 0; j < 8; j++)
            uu[j] = ((const uint2*)(h + (size_t)rr[j] * FDIM))[lane];
#pragma unroll
        for (int j = 0; j < 8; j++) {
            float2 f0 = __half22float2(*(__half2*)&uu[j].x);
            float2 f1 = __half22float2(*(__half2*)&uu[j].y);
            acc.x += ww[j] * f0.x;
            acc.y += ww[j] * f0.y;
            acc.z += ww[j] * f1.x;
            acc.w += ww[j] * f1.y;
        }
    }
    for (; e < end; e++) {
        int   r = g_src[e];
        float w = g_nrm[e];
        uint2 u = ((const uint2*)(h + (size_t)r * FDIM))[lane];
        float2 f0 = __half22float2(*(__half2*)&u.x);
        float2 f1 = __half22float2(*(__half2*)&u.y);
        acc.x += w * f0.x;
        acc.y += w * f0.y;
        acc.z += w * f1.x;
        acc.w += w * f1.y;
    }
    float4 bb = ((const float4*)bias)[lane];
    acc.x = fmaxf(acc.x + bb.x, 0.0f);
    acc.y = fmaxf(acc.y + bb.y, 0.0f);
    acc.z = fmaxf(acc.z + bb.z, 0.0f);
    acc.w = fmaxf(acc.w + bb.w, 0.0f);
    __half2 p0 = __floats2half2_rn(acc.x, acc.y);
    __half2 p1 = __floats2half2_rn(acc.z, acc.w);
    uint2 pk;
    pk.x = *(uint32_t*)&p0;
    pk.y = *(uint32_t*)&p1;
    ((uint2*)(out + (size_t)node * FDIM))[lane] = pk;
}

// ---------------- pooling (batch is sorted -> segmented sum, fp16 input) -------------
__global__ void k_pool_zero(float* __restrict__ out) {
    int i = blockIdx.x * blockDim.x + threadIdx.x;
    if (i < N_GRAPHS * FDIM) out[i] = 0.0f;
    if (i < N_GRAPHS) g_cnt[i] = 0.0f;
}
__global__ void k_pool_seg(const __half* __restrict__ a, const void* __restrict__ batch,
                           float* __restrict__ out) {
    int b0 = blockIdx.x * 128;
    if (b0 >= N_NODES) return;
    int f = threadIdx.x;
    int nend = min(N_NODES, b0 + 128);
    int is64 = g_is64;

    float acc = 0.0f;
    int cnt = 0;
    int cur = load_idx(batch, b0, is64);
    for (int node = b0; node < nend; node++) {
        int g = load_idx(batch, node, is64);
        if (g != cur) {
            atomicAdd(&out[(size_t)cur * FDIM + f], acc);
            if (f == 0) atomicAdd(&g_cnt[cur], (float)cnt);
            acc = 0.0f; cnt = 0; cur = g;
        }
        acc += __half2float(a[(size_t)node * FDIM + f]);
        cnt++;
    }
    atomicAdd(&out[(size_t)cur * FDIM + f], acc);
    if (f == 0) atomicAdd(&g_cnt[cur], (float)cnt);
}
__global__ void k_pool_div(float* __restrict__ out) {
    int i = blockIdx.x * blockDim.x + threadIdx.x;
    if (i < N_GRAPHS * FDIM) out[i] /= fmaxf(g_cnt[i >> 7], 1.0f);
}

// ---------------- launch ----------------
extern "C" void kernel_launch(void* const* d_in, const int* in_sizes, int n_in,
                              void* d_out, int out_size) {
    const float* x = nullptr;
    const float* W[4] = {nullptr, nullptr, nullptr, nullptr};
    const float* b[4] = {nullptr, nullptr, nullptr, nullptr};
    const void* ei = nullptr;
    const void* batch = nullptr;
    int nw = 0, nb = 0;
    for (int i = 0; i < n_in; i++) {
        switch (in_sizes[i]) {
            case N_NODES * FDIM:      x = (const float*)d_in[i]; break;
            case FDIM * FDIM:         if (nw < 4) W[nw++] = (const float*)d_in[i]; break;
            case FDIM:                if (nb < 4) b[nb++] = (const float*)d_in[i]; break;
            case 2 * N_EDGES:         ei = d_in[i]; break;
            case N_NODES:             batch = d_in[i]; break;
            default: break;
        }
    }
    if (!x && n_in >= 11) {
        x = (const float*)d_in[0];
        W[0] = (const float*)d_in[1]; b[0] = (const float*)d_in[2];
        W[1] = (const float*)d_in[3]; b[1] = (const float*)d_in[4];
        W[2] = (const float*)d_in[5]; b[2] = (const float*)d_in[6];
        W[3] = (const float*)d_in[7]; b[3] = (const float*)d_in[8];
        ei = d_in[9]; batch = d_in[10];
    }
    float* out = (float*)d_out;

    __half* gh; cudaGetSymbolAddress((void**)&gh, g_h);
    __half* ga; cudaGetSymbolAddress((void**)&ga, g_a);
    __half* gw; cudaGetSymbolAddress((void**)&gw, g_W16);

    const int GEMM_SMEM = (128 * LDSW + 2 * 128 * LDSA) * (int)sizeof(__half);  // 104448
    const int GEMM_F32_SMEM = (128 * LDSW + 128 * LDSA) * (int)sizeof(__half);  // 69632
    cudaFuncSetAttribute(k_gemm_wmma, cudaFuncAttributeMaxDynamicSharedMemorySize, GEMM_SMEM);
    cudaFuncSetAttribute(k_gemm_f32,  cudaFuncAttributeMaxDynamicSharedMemorySize, GEMM_F32_SMEM);

    const int TPB = 256;
    const int agg_blocks = (N_NODES * 32 + TPB - 1) / TPB;
    const int seg_blocks = (N_NODES + 127) / 128;

    const bool fork = g_sh.ok;
    cudaStream_t s2 = fork ? g_sh.s2 : (cudaStream_t)0;

    // detect first (preproc needs g_is64), then fork preproc to side stream
    k_detect<<<1, 32>>>((const int*)ei);
    if (fork) {
        cudaEventRecord(g_sh.ef, 0);
        cudaStreamWaitEvent(s2, g_sh.ef, 0);
    }

    // side stream: graph preprocessing (dis fused into scan1) + pool zero
    k_zero_deg<<<(N_NODES + TPB - 1) / TPB, TPB, 0, s2>>>();
    k_count<<<(N_EDGES + TPB - 1) / TPB, TPB, 0, s2>>>(ei);
    k_scan1<<<NB_SCAN, 1024, 0, s2>>>();
    k_scan2<<<1, 128, 0, s2>>>();
    k_scan3<<<NB_SCAN, 1024, 0, s2>>>();
    k_fill<<<(N_EDGES + TPB - 1) / TPB, TPB, 0, s2>>>(ei);
    k_pool_zero<<<(N_GRAPHS * FDIM + TPB - 1) / TPB, TPB, 0, s2>>>(out);
    if (fork) cudaEventRecord(g_sh.ej, s2);

    // main stream: W prep + layer-1 GEMM directly from fp32 x (xconv eliminated)
    k_wprep<<<(4 * FDIM * FDIM + TPB - 1) / TPB, TPB>>>(W[0], W[1], W[2], W[3]);
    k_gemm_f32<<<GEMM_GRID, 512, GEMM_F32_SMEM>>>(x, gw + 0 * FDIM * FDIM, gh, N_NODES);

    if (fork) cudaStreamWaitEvent(0, g_sh.ej, 0);   // join: agg needs CSR

    // layers (flat schedule — R15 proven best)
    k_agg<<<agg_blocks, TPB>>>(gh, b[0], ga);
    k_gemm_wmma<<<GEMM_GRID, 512, GEMM_SMEM>>>(ga, gw + 1 * FDIM * FDIM, gh, N_NODES);
    k_agg<<<agg_blocks, TPB>>>(gh, b[1], ga);
    k_gemm_wmma<<<GEMM_GRID, 512, GEMM_SMEM>>>(ga, gw + 2 * FDIM * FDIM, gh, N_NODES);
    k_agg<<<agg_blocks, TPB>>>(gh, b[2], ga);
    k_gemm_wmma<<<GEMM_GRID, 512, GEMM_SMEM>>>(ga, gw + 3 * FDIM * FDIM, gh, N_NODES);
    k_agg<<<agg_blocks, TPB>>>(gh, b[3], ga);

    // pooling
    k_pool_seg<<<seg_blocks, 128>>>(ga, batch, out);
    k_pool_div<<<(N_GRAPHS * FDIM + TPB - 1) / TPB, TPB>>>(out);
}